// round 11
// baseline (speedup 1.0000x reference)
#include <cuda_runtime.h>
#include <math.h>

// ---------------------------------------------------------------------------
// RSSM observe_rollout: B=256, T=64 (63 steps), D=1024, S=64, A=32, E=1024, H=1024
// Output: [63, 256, 1408] fp32 = (h_new | pmean | pstd | pstoch | qmean | qstd | qstoch)
// ---------------------------------------------------------------------------

#define TSTEPS   63
#define BATCH    256
#define DDIM     1024
#define SDIM     64
#define ADIM     32
#define EDIM     1024
#define HDIM     1024
#define OUTCOLS  1408   // D + 6S

// ---------------- scratch (device global; no allocation at runtime) --------
// float offsets into g_scratch
#define OFF_E      0L                      // 256*1024
#define OFF_GI     262144L                 // 256*3072
#define OFF_GH     1048576L                // 256*3072
#define OFF_H      1835008L                // 256*1024
#define OFF_S      2097152L                // 256*64
#define OFF_HP     2113536L                // 256*1024
#define OFF_HQ     2375680L                // 256*1024
#define OFF_PART   2637824L                // 2 heads * 8 splits * 256*128
#define OFF_PRESA  3162112L                // 63*256*1024
#define OFF_PREQ   19677184L               // 63*256*1024
#define SCRATCH_TOTAL 36192256L

__device__ float g_scratch[SCRATCH_TOTAL];

// ---------------- generic fused SGEMM -------------------------------------
// C[M,N] = ACT( A[M,K] @ W[N,K]^T + bias + Cinit ), with optional split-K
// A row addressing: rb==0 -> row*sI ; else (row/rb)*sO + (row%rb)*sI
struct GP {
    const float* A;  int rb;  long sO;  long sI;
    const float* W;  int ldw;
    const float* bias;
    const float* Cinit; int ldci;
    float* C; int ldc; long splitStride;
};

__device__ __forceinline__ const float* rowp(const GP& p, int row) {
    if (p.rb == 0) return p.A + (long)row * p.sI;
    int o = row / p.rb;
    int i = row - o * p.rb;
    return p.A + (long)o * p.sO + (long)i * p.sI;
}

template<int BM, int BN, int BK, int TM, int TN, int ACT>
__global__ void __launch_bounds__((BM/TM)*(BN/TN))
gemm_k(GP p0, GP p1, int nsplit, int kc)
{
    constexpr int NT  = (BM/TM)*(BN/TN);
    constexpr int KF4 = BK/4;
    const GP p = (blockIdx.z / nsplit) ? p1 : p0;
    const int split = blockIdx.z % nsplit;
    const int kBeg  = split * kc;
    const int bn0 = blockIdx.x * BN;
    const int bm0 = blockIdx.y * BM;

    __shared__ float As[BK][BM + 4];
    __shared__ float Bs[BK][BN + 4];

    float acc[TM][TN];
#pragma unroll
    for (int i = 0; i < TM; i++)
#pragma unroll
        for (int j = 0; j < TN; j++) acc[i][j] = 0.f;

    const int tid = threadIdx.x;
    const int tx  = tid % (BN/TN);
    const int ty  = tid / (BN/TN);

    for (int kt = kBeg; kt < kBeg + kc; kt += BK) {
        // load A tile (transposed into smem)
#pragma unroll
        for (int it = 0; it < (BM*BK/4)/NT; it++) {
            int i  = tid + it*NT;
            int r  = i / KF4;
            int c4 = i % KF4;
            const float* ap = rowp(p, bm0 + r) + kt + c4*4;
            float4 v = *reinterpret_cast<const float4*>(ap);
            As[c4*4+0][r] = v.x; As[c4*4+1][r] = v.y;
            As[c4*4+2][r] = v.z; As[c4*4+3][r] = v.w;
        }
        // load W tile (W is [N,K] row-major -> Bs[k][n])
#pragma unroll
        for (int it = 0; it < (BN*BK/4)/NT; it++) {
            int i  = tid + it*NT;
            int n  = i / KF4;
            int c4 = i % KF4;
            float4 v = *reinterpret_cast<const float4*>(
                p.W + (long)(bn0 + n) * p.ldw + kt + c4*4);
            Bs[c4*4+0][n] = v.x; Bs[c4*4+1][n] = v.y;
            Bs[c4*4+2][n] = v.z; Bs[c4*4+3][n] = v.w;
        }
        __syncthreads();

#pragma unroll
        for (int k = 0; k < BK; k++) {
            float a[TM], b[TN];
#pragma unroll
            for (int i = 0; i < TM; i += 4) {
                float4 v = *reinterpret_cast<const float4*>(&As[k][ty*TM + i]);
                a[i]=v.x; a[i+1]=v.y; a[i+2]=v.z; a[i+3]=v.w;
            }
#pragma unroll
            for (int j = 0; j < TN; j += 4) {
                float4 v = *reinterpret_cast<const float4*>(&Bs[k][tx*TN + j]);
                b[j]=v.x; b[j+1]=v.y; b[j+2]=v.z; b[j+3]=v.w;
            }
#pragma unroll
            for (int i = 0; i < TM; i++)
#pragma unroll
                for (int j = 0; j < TN; j++)
                    acc[i][j] = fmaf(a[i], b[j], acc[i][j]);
        }
        __syncthreads();
    }

    float* Cp = p.C + (long)split * p.splitStride;
#pragma unroll
    for (int i = 0; i < TM; i++) {
        int row = bm0 + ty*TM + i;
#pragma unroll
        for (int j = 0; j < TN; j++) {
            int col = bn0 + tx*TN + j;
            float c = acc[i][j];
            if (p.bias)  c += p.bias[col];
            if (p.Cinit) c += p.Cinit[(long)row * p.ldci + col];
            if (ACT)     c = (c > 0.f) ? c : expm1f(c);
            Cp[(long)row * p.ldc + col] = c;
        }
    }
}

// ---------------- elementwise kernels --------------------------------------
__global__ void zero_k(float* p, int n) {
    int i = blockIdx.x * blockDim.x + threadIdx.x;
    if (i < n) p[i] = 0.f;
}

__device__ __forceinline__ float sigm(float x) { return 1.f / (1.f + expf(-x)); }
__device__ __forceinline__ float softplus_f(float x) {
    return fmaxf(x, 0.f) + log1pf(expf(-fabsf(x)));
}

// GRU gate: h_new = (1-z)*n + z*h ; writes g_h (in place) and out[t][:, :1024]
__global__ void gate_k(const float* __restrict__ gi, const float* __restrict__ gh,
                       float* __restrict__ h, float* __restrict__ out_t)
{
    int idx = blockIdx.x * blockDim.x + threadIdx.x;   // 0 .. 256*1024-1
    int b = idx >> 10;
    int j = idx & 1023;
    long base = (long)b * 3072;
    float ir = gi[base + j],        hr = gh[base + j];
    float iz = gi[base + 1024 + j], hz = gh[base + 1024 + j];
    float ia = gi[base + 2048 + j], ha = gh[base + 2048 + j];
    float r = sigm(ir + hr);
    float z = sigm(iz + hz);
    float n = tanhf(ia + r * ha);
    float hn = (1.f - z) * n + z * h[(long)b * 1024 + j];
    h[(long)b * 1024 + j] = hn;
    out_t[(long)b * OUTCOLS + j] = hn;
}

// reduce split-K partials of pm/qm, softplus+reparam, emit outputs + next s
__global__ void epi_k(const float* __restrict__ part,
                      const float* __restrict__ bp2, const float* __restrict__ bq2,
                      const float* __restrict__ np,  const float* __restrict__ nq,
                      float* __restrict__ out_t, float* __restrict__ s_next)
{
    int idx = blockIdx.x * blockDim.x + threadIdx.x;   // 0 .. 256*64-1
    int b = idx >> 6;
    int j = idx & 63;
    const float* pp = part;
    const float* pq = part + 8L * 256 * 128;
    float pmean = 0.f, praw = 0.f, qmean = 0.f, qraw = 0.f;
#pragma unroll
    for (int s = 0; s < 8; s++) {
        const float* rp = pp + (long)s * (256 * 128) + (long)b * 128;
        const float* rq = pq + (long)s * (256 * 128) + (long)b * 128;
        pmean += rp[j];  praw += rp[64 + j];
        qmean += rq[j];  qraw += rq[64 + j];
    }
    pmean += bp2[j];  praw += bp2[64 + j];
    qmean += bq2[j];  qraw += bq2[64 + j];
    float pstd = softplus_f(praw) + 0.1f;
    float qstd = softplus_f(qraw) + 0.1f;
    float pst = pmean + pstd * np[(long)b * 64 + j];
    float qst = qmean + qstd * nq[(long)b * 64 + j];
    float* o = out_t + (long)b * OUTCOLS + 1024;
    o[j]        = pmean;
    o[64  + j]  = pstd;
    o[128 + j]  = pst;
    o[192 + j]  = qmean;
    o[256 + j]  = qstd;
    o[320 + j]  = qst;
    s_next[(long)b * 64 + j] = qst;
}

// ---------------- host orchestration ---------------------------------------
static GP mk(const float* A, int rb, long sO, long sI,
             const float* W, int ldw, const float* bias,
             const float* Cinit, int ldci,
             float* C, int ldc, long ss)
{
    GP p; p.A=A; p.rb=rb; p.sO=sO; p.sI=sI; p.W=W; p.ldw=ldw; p.bias=bias;
    p.Cinit=Cinit; p.ldci=ldci; p.C=C; p.ldc=ldc; p.splitStride=ss;
    return p;
}

extern "C" void kernel_launch(void* const* d_in, const int* in_sizes, int n_in,
                              void* d_out, int out_size)
{
    const float* obs  = (const float*)d_in[0];   // [256,64,1024]
    const float* act  = (const float*)d_in[1];   // [256,64,32]
    const float* np   = (const float*)d_in[2];   // [63,256,64]
    const float* nq   = (const float*)d_in[3];   // [63,256,64]
    const float* Wsa  = (const float*)d_in[4];   // [1024,96]
    const float* bsa  = (const float*)d_in[5];
    const float* Wih  = (const float*)d_in[6];   // [3072,1024]
    const float* bih  = (const float*)d_in[7];
    const float* Whh  = (const float*)d_in[8];   // [3072,1024]
    const float* bhh  = (const float*)d_in[9];
    const float* Wp1  = (const float*)d_in[10];  // [1024,1024]
    const float* bp1  = (const float*)d_in[11];
    const float* Wp2  = (const float*)d_in[12];  // [128,1024]
    const float* bp2  = (const float*)d_in[13];
    const float* Wq1  = (const float*)d_in[14];  // [1024,2048]
    const float* bq1  = (const float*)d_in[15];
    const float* Wq2  = (const float*)d_in[16];  // [128,1024]
    const float* bq2  = (const float*)d_in[17];
    float* out = (float*)d_out;

    void* sp = nullptr;
    cudaGetSymbolAddress(&sp, g_scratch);
    float* SB = (float*)sp;
    float* e_buf  = SB + OFF_E;
    float* gi_buf = SB + OFF_GI;
    float* gh_buf = SB + OFF_GH;
    float* h_buf  = SB + OFF_H;
    float* s_buf  = SB + OFF_S;
    float* hp_buf = SB + OFF_HP;
    float* hq_buf = SB + OFF_HQ;
    float* part   = SB + OFF_PART;
    float* pre_sa = SB + OFF_PRESA;
    float* pre_q  = SB + OFF_PREQ;

    // h0 = 0, s0 = 0 (g_h and g_s are contiguous in scratch)
    zero_k<<<(262144 + 16384 + 255) / 256, 256>>>(h_buf, 262144 + 16384);

    // ---- precompute obs/action contributions for all 63 steps ----
    // pre_sa[t,b,:] = act[b,t,:] @ W_sa[:,64:96]^T + b_sa   (M=16128, K=32)
    {
        GP p = mk(act, 256, /*sO=*/ADIM, /*sI=*/64L * ADIM,
                  Wsa + 64, 96, bsa, nullptr, 0, pre_sa, 1024, 0);
        gemm_k<64,64,16,4,4,0><<<dim3(16, 252, 1), 256>>>(p, p, 1, 32);
    }
    // pre_q[t,b,:] = obs[b,t+1,:] @ Wq1[:,1024:2048]^T + bq1  (M=16128, K=1024)
    {
        GP p = mk(obs + 1024, 256, /*sO=*/EDIM, /*sI=*/64L * EDIM,
                  Wq1 + 1024, 2048, bq1, nullptr, 0, pre_q, 1024, 0);
        gemm_k<128,128,16,8,8,0><<<dim3(8, 126, 1), 256>>>(p, p, 1, 1024);
    }

    // ---- 63 sequential steps ----
    for (int t = 0; t < TSTEPS; t++) {
        float* out_t = out + (long)t * BATCH * OUTCOLS;

        // e = elu( s @ W_sa[:, :64]^T + pre_sa[t] )
        {
            GP p = mk(s_buf, 0, 0, 64,
                      Wsa, 96, nullptr, pre_sa + (long)t * 262144, 1024,
                      e_buf, 1024, 0);
            gemm_k<64,64,16,4,4,1><<<dim3(16, 4, 1), 256>>>(p, p, 1, 64);
        }
        // gi = e @ W_ih^T + b_ih ; gh = h @ W_hh^T + b_hh  (paired launch)
        {
            GP p0 = mk(e_buf, 0, 0, 1024, Wih, 1024, bih, nullptr, 0, gi_buf, 3072, 0);
            GP p1 = mk(h_buf, 0, 0, 1024, Whh, 1024, bhh, nullptr, 0, gh_buf, 3072, 0);
            gemm_k<128,128,16,8,8,0><<<dim3(24, 2, 2), 256>>>(p0, p1, 1, 1024);
        }
        // GRU gate -> h_new (writes g_h and out[t][:, :1024])
        gate_k<<<1024, 256>>>(gi_buf, gh_buf, h_buf, out_t);

        // hp = elu(h @ Wp1^T + bp1) ; hq = elu(h @ Wq1[:, :1024]^T + pre_q[t])
        {
            GP p0 = mk(h_buf, 0, 0, 1024, Wp1, 1024, bp1, nullptr, 0, hp_buf, 1024, 0);
            GP p1 = mk(h_buf, 0, 0, 1024, Wq1, 2048, nullptr,
                       pre_q + (long)t * 262144, 1024, hq_buf, 1024, 0);
            gemm_k<64,64,16,4,4,1><<<dim3(16, 4, 2), 256>>>(p0, p1, 1, 1024);
        }
        // pm/qm partials (split-K = 8, deterministic reduction in epilogue)
        {
            GP p0 = mk(hp_buf, 0, 0, 1024, Wp2, 1024, nullptr, nullptr, 0,
                       part, 128, 256L * 128);
            GP p1 = mk(hq_buf, 0, 0, 1024, Wq2, 1024, nullptr, nullptr, 0,
                       part + 8L * 256 * 128, 128, 256L * 128);
            gemm_k<64,64,16,4,4,0><<<dim3(2, 4, 16), 256>>>(p0, p1, 8, 128);
        }
        // reduce + softplus + reparam + write outputs + next s
        epi_k<<<64, 256>>>(part, bp2, bq2,
                           np + (long)t * BATCH * SDIM,
                           nq + (long)t * BATCH * SDIM,
                           out_t, s_buf);
    }
}

// round 12
// speedup vs baseline: 1.3921x; 1.3921x over previous
#include <cuda_runtime.h>
#include <math.h>

// ---------------------------------------------------------------------------
// RSSM observe_rollout: B=256, T=64 (63 steps), D=1024, S=64, A=32, E=1024, H=1024
// Output: [63, 256, 1408] fp32 = (h_new | pmean | pstd | pstoch | qmean | qstd | qstoch)
// R11: packed fma.rn.f32x2 everywhere + wave-balanced grids (split-K gi/gh,
//      64x64 single-wave hp/hq, split-K=32 p2/q2 reduced in epilogue kernels)
// ---------------------------------------------------------------------------

#define TSTEPS   63
#define BATCH    256
#define OUTCOLS  1408   // D + 6S

// ---------------- scratch (device global; no runtime allocation) -----------
#define OFF_E      0L                      // 256*1024
#define OFF_GIP    262144L                 // 3 * 256*3072
#define OFF_GHP    2621440L                // 3 * 256*3072
#define OFF_H      4980736L                // 256*1024
#define OFF_S      5242880L                // 256*64
#define OFF_HP     5259264L                // 256*1024
#define OFF_HQ     5521408L                // 256*1024
#define OFF_PART   5783552L                // 2 heads * 32 splits * 256*128
#define OFF_PRESA  7880704L                // 63*256*1024
#define OFF_PREQ   24395776L               // 63*256*1024
#define SCRATCH_TOTAL 40910848L

__device__ float g_scratch[SCRATCH_TOTAL];

// ---------------- packed fp32x2 FMA helpers --------------------------------
typedef unsigned long long u64t;

__device__ __forceinline__ u64t pack2(float x, float y) {
    u64t r;
    asm("mov.b64 %0, {%1, %2};" : "=l"(r) : "f"(x), "f"(y));
    return r;
}
__device__ __forceinline__ void unpack2(u64t v, float& x, float& y) {
    asm("mov.b64 {%0, %1}, %2;" : "=f"(x), "=f"(y) : "l"(v));
}
__device__ __forceinline__ void fma2(u64t& c, u64t a, u64t b) {
    asm("fma.rn.f32x2 %0, %1, %2, %0;" : "+l"(c) : "l"(a), "l"(b));
}

// ---------------- generic fused SGEMM (f32x2 core) --------------------------
// C[M,N] = ACT( A[M,K] @ W[N,K]^T + bias + Cinit ), optional split-K partials
// A row addressing: rb==0 -> row*sI ; else (row/rb)*sO + (row%rb)*sI
struct GP {
    const float* A;  int rb;  long sO;  long sI;
    const float* W;  int ldw;
    const float* bias;
    const float* Cinit; int ldci;
    float* C; int ldc; long splitStride;
};

__device__ __forceinline__ const float* rowp(const GP& p, int row) {
    if (p.rb == 0) return p.A + (long)row * p.sI;
    int o = row / p.rb;
    int i = row - o * p.rb;
    return p.A + (long)o * p.sO + (long)i * p.sI;
}

template<int BM, int BN, int BK, int TM, int TN, int ACT>
__global__ void __launch_bounds__((BM/TM)*(BN/TN))
gemm2_k(GP p0, GP p1, int nsplit, int kc0, int kcr)
{
    constexpr int NT  = (BM/TM)*(BN/TN);
    constexpr int KF4 = BK/4;
    const GP p = (blockIdx.z / nsplit) ? p1 : p0;
    const int split = blockIdx.z % nsplit;
    const int kBeg  = (split == 0) ? 0 : kc0 + (split - 1) * kcr;
    const int kcur  = (split == 0) ? kc0 : kcr;
    const int bn0 = blockIdx.x * BN;
    const int bm0 = blockIdx.y * BM;

    __shared__ float As[BK][BM + 4];
    __shared__ float Bs[BK][BN + 4];

    u64t acc2[TM][TN/2];
#pragma unroll
    for (int i = 0; i < TM; i++)
#pragma unroll
        for (int j = 0; j < TN/2; j++) acc2[i][j] = 0ULL;

    const int tid = threadIdx.x;
    const int tx  = tid % (BN/TN);
    const int ty  = tid / (BN/TN);

    for (int kt = kBeg; kt < kBeg + kcur; kt += BK) {
        // load A tile (transposed into smem)
#pragma unroll
        for (int it = 0; it < (BM*BK/4)/NT; it++) {
            int i  = tid + it*NT;
            int r  = i / KF4;
            int c4 = i % KF4;
            const float* ap = rowp(p, bm0 + r) + kt + c4*4;
            float4 v = *reinterpret_cast<const float4*>(ap);
            As[c4*4+0][r] = v.x; As[c4*4+1][r] = v.y;
            As[c4*4+2][r] = v.z; As[c4*4+3][r] = v.w;
        }
        // load W tile (W is [N,K] row-major -> Bs[k][n])
#pragma unroll
        for (int it = 0; it < (BN*BK/4)/NT; it++) {
            int i  = tid + it*NT;
            int n  = i / KF4;
            int c4 = i % KF4;
            float4 v = *reinterpret_cast<const float4*>(
                p.W + (long)(bn0 + n) * p.ldw + kt + c4*4);
            Bs[c4*4+0][n] = v.x; Bs[c4*4+1][n] = v.y;
            Bs[c4*4+2][n] = v.z; Bs[c4*4+3][n] = v.w;
        }
        __syncthreads();

#pragma unroll
        for (int k = 0; k < BK; k++) {
            float a[TM];
            u64t  b2[TN/2];
#pragma unroll
            for (int i = 0; i < TM; i += 4) {
                float4 v = *reinterpret_cast<const float4*>(&As[k][ty*TM + i]);
                a[i]=v.x; a[i+1]=v.y; a[i+2]=v.z; a[i+3]=v.w;
            }
#pragma unroll
            for (int j = 0; j < TN; j += 4) {
                float4 v = *reinterpret_cast<const float4*>(&Bs[k][tx*TN + j]);
                b2[j/2]     = pack2(v.x, v.y);
                b2[j/2 + 1] = pack2(v.z, v.w);
            }
#pragma unroll
            for (int i = 0; i < TM; i++) {
                u64t a2 = pack2(a[i], a[i]);
#pragma unroll
                for (int jp = 0; jp < TN/2; jp++)
                    fma2(acc2[i][jp], a2, b2[jp]);
            }
        }
        __syncthreads();
    }

    float* Cp = p.C + (long)split * p.splitStride;
#pragma unroll
    for (int i = 0; i < TM; i++) {
        int row = bm0 + ty*TM + i;
#pragma unroll
        for (int jp = 0; jp < TN/2; jp++) {
            float c0, c1;
            unpack2(acc2[i][jp], c0, c1);
            int col = bn0 + tx*TN + 2*jp;
            if (p.bias)  { c0 += p.bias[col]; c1 += p.bias[col+1]; }
            if (p.Cinit) {
                const float* ci = p.Cinit + (long)row * p.ldci + col;
                c0 += ci[0]; c1 += ci[1];
            }
            if (ACT) {
                c0 = (c0 > 0.f) ? c0 : expm1f(c0);
                c1 = (c1 > 0.f) ? c1 : expm1f(c1);
            }
            float* cp = Cp + (long)row * p.ldc + col;
            cp[0] = c0; cp[1] = c1;
        }
    }
}

// ---------------- elementwise kernels --------------------------------------
__global__ void zero_k(float* p, int n) {
    int i = blockIdx.x * blockDim.x + threadIdx.x;
    if (i < n) p[i] = 0.f;
}

__device__ __forceinline__ float sigm(float x) { return 1.f / (1.f + expf(-x)); }
__device__ __forceinline__ float softplus_f(float x) {
    return fmaxf(x, 0.f) + log1pf(expf(-fabsf(x)));
}

// GRU gate with split-K(3) reduction of gi/gh partials.
// h_new = (1-z)*n + z*h ; writes h (in place) and out[t][:, :1024]
__global__ void gate_k(const float* __restrict__ giP, const float* __restrict__ ghP,
                       const float* __restrict__ bih, const float* __restrict__ bhh,
                       float* __restrict__ h, float* __restrict__ out_t)
{
    int idx = blockIdx.x * blockDim.x + threadIdx.x;   // 0 .. 256*1024-1
    int b = idx >> 10;
    int j = idx & 1023;
    long base = (long)b * 3072;
    float ir = bih[j],        hr = bhh[j];
    float iz = bih[1024 + j], hz = bhh[1024 + j];
    float ia = bih[2048 + j], ha = bhh[2048 + j];
#pragma unroll
    for (int s = 0; s < 3; s++) {
        const float* gi = giP + (long)s * (256L * 3072) + base;
        const float* gh = ghP + (long)s * (256L * 3072) + base;
        ir += gi[j];        hr += gh[j];
        iz += gi[1024 + j]; hz += gh[1024 + j];
        ia += gi[2048 + j]; ha += gh[2048 + j];
    }
    float r = sigm(ir + hr);
    float z = sigm(iz + hz);
    float n = tanhf(ia + r * ha);
    float hn = (1.f - z) * n + z * h[(long)b * 1024 + j];
    h[(long)b * 1024 + j] = hn;
    out_t[(long)b * OUTCOLS + j] = hn;
}

// reduce split-K(32) partials of pm/qm, softplus+reparam, emit outputs + next s
__global__ void epi_k(const float* __restrict__ part,
                      const float* __restrict__ bp2, const float* __restrict__ bq2,
                      const float* __restrict__ np,  const float* __restrict__ nq,
                      float* __restrict__ out_t, float* __restrict__ s_next)
{
    int idx = blockIdx.x * blockDim.x + threadIdx.x;   // 0 .. 256*64-1
    int b = idx >> 6;
    int j = idx & 63;
    const float* pp = part;
    const float* pq = part + 32L * 256 * 128;
    float pmean = 0.f, praw = 0.f, qmean = 0.f, qraw = 0.f;
#pragma unroll
    for (int s = 0; s < 32; s++) {
        const float* rp = pp + (long)s * (256 * 128) + (long)b * 128;
        const float* rq = pq + (long)s * (256 * 128) + (long)b * 128;
        pmean += rp[j];  praw += rp[64 + j];
        qmean += rq[j];  qraw += rq[64 + j];
    }
    pmean += bp2[j];  praw += bp2[64 + j];
    qmean += bq2[j];  qraw += bq2[64 + j];
    float pstd = softplus_f(praw) + 0.1f;
    float qstd = softplus_f(qraw) + 0.1f;
    float pst = pmean + pstd * np[(long)b * 64 + j];
    float qst = qmean + qstd * nq[(long)b * 64 + j];
    float* o = out_t + (long)b * OUTCOLS + 1024;
    o[j]        = pmean;
    o[64  + j]  = pstd;
    o[128 + j]  = pst;
    o[192 + j]  = qmean;
    o[256 + j]  = qstd;
    o[320 + j]  = qst;
    s_next[(long)b * 64 + j] = qst;
}

// ---------------- host orchestration ---------------------------------------
static GP mk(const float* A, int rb, long sO, long sI,
             const float* W, int ldw, const float* bias,
             const float* Cinit, int ldci,
             float* C, int ldc, long ss)
{
    GP p; p.A=A; p.rb=rb; p.sO=sO; p.sI=sI; p.W=W; p.ldw=ldw; p.bias=bias;
    p.Cinit=Cinit; p.ldci=ldci; p.C=C; p.ldc=ldc; p.splitStride=ss;
    return p;
}

extern "C" void kernel_launch(void* const* d_in, const int* in_sizes, int n_in,
                              void* d_out, int out_size)
{
    const float* obs  = (const float*)d_in[0];   // [256,64,1024]
    const float* act  = (const float*)d_in[1];   // [256,64,32]
    const float* np   = (const float*)d_in[2];   // [63,256,64]
    const float* nq   = (const float*)d_in[3];   // [63,256,64]
    const float* Wsa  = (const float*)d_in[4];   // [1024,96]
    const float* bsa  = (const float*)d_in[5];
    const float* Wih  = (const float*)d_in[6];   // [3072,1024]
    const float* bih  = (const float*)d_in[7];
    const float* Whh  = (const float*)d_in[8];   // [3072,1024]
    const float* bhh  = (const float*)d_in[9];
    const float* Wp1  = (const float*)d_in[10];  // [1024,1024]
    const float* bp1  = (const float*)d_in[11];
    const float* Wp2  = (const float*)d_in[12];  // [128,1024]
    const float* bp2  = (const float*)d_in[13];
    const float* Wq1  = (const float*)d_in[14];  // [1024,2048]
    const float* bq1  = (const float*)d_in[15];
    const float* Wq2  = (const float*)d_in[16];  // [128,1024]
    const float* bq2  = (const float*)d_in[17];
    float* out = (float*)d_out;

    void* sp = nullptr;
    cudaGetSymbolAddress(&sp, g_scratch);
    float* SB = (float*)sp;
    float* e_buf  = SB + OFF_E;
    float* giP    = SB + OFF_GIP;
    float* ghP    = SB + OFF_GHP;
    float* h_buf  = SB + OFF_H;
    float* s_buf  = SB + OFF_S;
    float* hp_buf = SB + OFF_HP;
    float* hq_buf = SB + OFF_HQ;
    float* part   = SB + OFF_PART;
    float* pre_sa = SB + OFF_PRESA;
    float* pre_q  = SB + OFF_PREQ;

    // h0 = 0, s0 = 0 (h and s contiguous in scratch)
    zero_k<<<(262144 + 16384 + 255) / 256, 256>>>(h_buf, 262144 + 16384);

    // ---- precompute obs/action contributions for all 63 steps ----
    // pre_sa[t,b,:] = act[b,t,:] @ W_sa[:,64:96]^T + b_sa   (M=16128, K=32)
    {
        GP p = mk(act, 256, /*sO=*/32, /*sI=*/64L * 32,
                  Wsa + 64, 96, bsa, nullptr, 0, pre_sa, 1024, 0);
        gemm2_k<64,64,16,4,4,0><<<dim3(16, 252, 1), 256>>>(p, p, 1, 32, 32);
    }
    // pre_q[t,b,:] = obs[b,t+1,:] @ Wq1[:,1024:2048]^T + bq1  (M=16128, K=1024)
    {
        GP p = mk(obs + 1024, 256, /*sO=*/1024, /*sI=*/64L * 1024,
                  Wq1 + 1024, 2048, bq1, nullptr, 0, pre_q, 1024, 0);
        gemm2_k<128,128,16,8,8,0><<<dim3(8, 126, 1), 256>>>(p, p, 1, 1024, 1024);
    }

    // ---- 63 sequential steps ----
    for (int t = 0; t < TSTEPS; t++) {
        float* out_t = out + (long)t * BATCH * OUTCOLS;

        // e = elu( s @ W_sa[:, :64]^T + pre_sa[t] )   M=256,N=1024,K=64
        {
            GP p = mk(s_buf, 0, 0, 64,
                      Wsa, 96, nullptr, pre_sa + (long)t * 262144, 1024,
                      e_buf, 1024, 0);
            gemm2_k<64,64,16,4,4,1><<<dim3(16, 4, 1), 256>>>(p, p, 1, 64, 64);
        }
        // gi/gh partials: split-K=3 (352/336/336), 288 blocks = 2 tight waves
        {
            GP p0 = mk(e_buf, 0, 0, 1024, Wih, 1024, nullptr, nullptr, 0,
                       giP, 3072, 256L * 3072);
            GP p1 = mk(h_buf, 0, 0, 1024, Whh, 1024, nullptr, nullptr, 0,
                       ghP, 3072, 256L * 3072);
            gemm2_k<128,128,16,8,8,0><<<dim3(24, 2, 6), 256>>>(p0, p1, 3, 352, 336);
        }
        // GRU gate + split-K reduction -> h_new (writes h and out[t][:, :1024])
        gate_k<<<1024, 256>>>(giP, ghP, bih, bhh, h_buf, out_t);

        // hp = elu(h @ Wp1^T + bp1) ; hq = elu(h @ Wq1[:, :1024]^T + pre_q[t])
        // 64x64 tiles -> 128 blocks, single wave, ELU fused, no split-K
        {
            GP p0 = mk(h_buf, 0, 0, 1024, Wp1, 1024, bp1, nullptr, 0, hp_buf, 1024, 0);
            GP p1 = mk(h_buf, 0, 0, 1024, Wq1, 2048, nullptr,
                       pre_q + (long)t * 262144, 1024, hq_buf, 1024, 0);
            gemm2_k<64,64,16,4,4,1><<<dim3(16, 4, 2), 256>>>(p0, p1, 1, 1024, 1024);
        }
        // pm/qm partials: split-K=32 (kc=32), 128 blocks, single wave
        {
            GP p0 = mk(hp_buf, 0, 0, 1024, Wp2, 1024, nullptr, nullptr, 0,
                       part, 128, 256L * 128);
            GP p1 = mk(hq_buf, 0, 0, 1024, Wq2, 1024, nullptr, nullptr, 0,
                       part + 32L * 256 * 128, 128, 256L * 128);
            gemm2_k<128,128,16,8,8,0><<<dim3(1, 2, 64), 256>>>(p0, p1, 32, 32, 32);
        }
        // reduce + softplus + reparam + write outputs + next s
        epi_k<<<64, 256>>>(part, bp2, bq2,
                           np + (long)t * BATCH * 64,
                           nq + (long)t * BATCH * 64,
                           out_t, s_buf);
    }
}

// round 13
// speedup vs baseline: 1.6540x; 1.1882x over previous
#include <cuda_runtime.h>
#include <cuda_bf16.h>
#include <math.h>

// ---------------------------------------------------------------------------
// RSSM observe_rollout: B=256, T=64 (63 steps), D=1024, S=64, A=32, E=1024, H=1024
// Output: [63, 256, 1408] fp32
// R12: big GEMMs on bf16 tensor cores (mma.sync m16n8k16) with hi/lo 3-term
//      compensated split; cp.async double buffering + ldmatrix.
// ---------------------------------------------------------------------------

#define TSTEPS   63
#define BATCH    256
#define OUTCOLS  1408

// ---------------- f32 scratch ----------------
#define F_PRESA  0L            // 63*256*1024
#define F_PREQ   16515072L     // 63*256*1024
#define F_GI     33030144L     // 256*3072
#define F_GH     33816576L     // 256*3072
#define F_H      34603008L     // 256*1024
#define F_S      34865152L     // 256*64
#define F_HP     34881536L     // 256*1024
#define F_HQ     35143680L     // 256*1024
#define F_PART   35405824L     // 2*32*256*128
#define F_TOTAL  37502976L
__device__ float g_f32[F_TOTAL];

// ---------------- bf16 scratch ----------------
#define B_OBSH   0L            // 256*64*1024
#define B_OBSL   16777216L
#define B_WIHH   33554432L     // 3072*1024
#define B_WIHL   36700160L
#define B_WHHH   39845888L
#define B_WHHL   42991616L
#define B_WP1H   46137344L     // 1024*1024
#define B_WP1L   47185920L
#define B_WQCH   48234496L     // Wq1[:, :1024]
#define B_WQCL   49283072L
#define B_WQOH   50331648L     // Wq1[:, 1024:2048]
#define B_WQOL   51380224L
#define B_EH     52428800L     // 256*1024
#define B_EL     52690944L
#define B_HH     52953088L     // 256*1024
#define B_HL     53215232L
#define B_TOTAL  53477376L
__device__ __nv_bfloat16 g_bf16[B_TOTAL];

// =================== fp32 SIMT GEMM (small ops) =============================
typedef unsigned long long u64t;
__device__ __forceinline__ u64t pack2(float x, float y) {
    u64t r; asm("mov.b64 %0, {%1, %2};" : "=l"(r) : "f"(x), "f"(y)); return r;
}
__device__ __forceinline__ void unpack2(u64t v, float& x, float& y) {
    asm("mov.b64 {%0, %1}, %2;" : "=f"(x), "=f"(y) : "l"(v));
}
__device__ __forceinline__ void fma2(u64t& c, u64t a, u64t b) {
    asm("fma.rn.f32x2 %0, %1, %2, %0;" : "+l"(c) : "l"(a), "l"(b));
}

struct GP {
    const float* A;  int rb;  long sO;  long sI;
    const float* W;  int ldw;
    const float* bias;
    const float* Cinit; int ldci;
    float* C; int ldc; long splitStride;
    __nv_bfloat16* Ch; __nv_bfloat16* Cl;
};

__device__ __forceinline__ const float* rowp(const GP& p, int row) {
    if (p.rb == 0) return p.A + (long)row * p.sI;
    int o = row / p.rb;
    int i = row - o * p.rb;
    return p.A + (long)o * p.sO + (long)i * p.sI;
}

template<int BM, int BN, int BK, int TM, int TN, int ACT, int OH>
__global__ void __launch_bounds__((BM/TM)*(BN/TN))
gemm2_k(GP p0, GP p1, int nsplit, int kc0, int kcr)
{
    constexpr int NT  = (BM/TM)*(BN/TN);
    constexpr int KF4 = BK/4;
    const GP p = (blockIdx.z / nsplit) ? p1 : p0;
    const int split = blockIdx.z % nsplit;
    const int kBeg  = (split == 0) ? 0 : kc0 + (split - 1) * kcr;
    const int kcur  = (split == 0) ? kc0 : kcr;
    const int bn0 = blockIdx.x * BN;
    const int bm0 = blockIdx.y * BM;

    __shared__ float As[BK][BM + 4];
    __shared__ float Bs[BK][BN + 4];

    u64t acc2[TM][TN/2];
#pragma unroll
    for (int i = 0; i < TM; i++)
#pragma unroll
        for (int j = 0; j < TN/2; j++) acc2[i][j] = 0ULL;

    const int tid = threadIdx.x;
    const int tx  = tid % (BN/TN);
    const int ty  = tid / (BN/TN);

    for (int kt = kBeg; kt < kBeg + kcur; kt += BK) {
#pragma unroll
        for (int it = 0; it < (BM*BK/4)/NT; it++) {
            int i  = tid + it*NT;
            int r  = i / KF4;
            int c4 = i % KF4;
            const float* ap = rowp(p, bm0 + r) + kt + c4*4;
            float4 v = *reinterpret_cast<const float4*>(ap);
            As[c4*4+0][r] = v.x; As[c4*4+1][r] = v.y;
            As[c4*4+2][r] = v.z; As[c4*4+3][r] = v.w;
        }
#pragma unroll
        for (int it = 0; it < (BN*BK/4)/NT; it++) {
            int i  = tid + it*NT;
            int n  = i / KF4;
            int c4 = i % KF4;
            float4 v = *reinterpret_cast<const float4*>(
                p.W + (long)(bn0 + n) * p.ldw + kt + c4*4);
            Bs[c4*4+0][n] = v.x; Bs[c4*4+1][n] = v.y;
            Bs[c4*4+2][n] = v.z; Bs[c4*4+3][n] = v.w;
        }
        __syncthreads();

#pragma unroll
        for (int k = 0; k < BK; k++) {
            float a[TM];
            u64t  b2[TN/2];
#pragma unroll
            for (int i = 0; i < TM; i += 4) {
                float4 v = *reinterpret_cast<const float4*>(&As[k][ty*TM + i]);
                a[i]=v.x; a[i+1]=v.y; a[i+2]=v.z; a[i+3]=v.w;
            }
#pragma unroll
            for (int j = 0; j < TN; j += 4) {
                float4 v = *reinterpret_cast<const float4*>(&Bs[k][tx*TN + j]);
                b2[j/2]     = pack2(v.x, v.y);
                b2[j/2 + 1] = pack2(v.z, v.w);
            }
#pragma unroll
            for (int i = 0; i < TM; i++) {
                u64t a2 = pack2(a[i], a[i]);
#pragma unroll
                for (int jp = 0; jp < TN/2; jp++)
                    fma2(acc2[i][jp], a2, b2[jp]);
            }
        }
        __syncthreads();
    }

    float* Cp = p.C ? p.C + (long)split * p.splitStride : nullptr;
#pragma unroll
    for (int i = 0; i < TM; i++) {
        int row = bm0 + ty*TM + i;
#pragma unroll
        for (int jp = 0; jp < TN/2; jp++) {
            float c0, c1;
            unpack2(acc2[i][jp], c0, c1);
            int col = bn0 + tx*TN + 2*jp;
            if (p.bias)  { c0 += p.bias[col]; c1 += p.bias[col+1]; }
            if (p.Cinit) {
                const float* ci = p.Cinit + (long)row * p.ldci + col;
                c0 += ci[0]; c1 += ci[1];
            }
            if (ACT) {
                c0 = (c0 > 0.f) ? c0 : expm1f(c0);
                c1 = (c1 > 0.f) ? c1 : expm1f(c1);
            }
            if (OH) {
                __nv_bfloat16 h0 = __float2bfloat16(c0);
                __nv_bfloat16 h1 = __float2bfloat16(c1);
                long o = (long)row * p.ldc + col;
                p.Ch[o]   = h0;
                p.Ch[o+1] = h1;
                p.Cl[o]   = __float2bfloat16(c0 - __bfloat162float(h0));
                p.Cl[o+1] = __float2bfloat16(c1 - __bfloat162float(h1));
            } else {
                float* cp = Cp + (long)row * p.ldc + col;
                cp[0] = c0; cp[1] = c1;
            }
        }
    }
}

// =================== bf16 3-term MMA GEMM ===================================
struct MP {
    const __nv_bfloat16* Ah; const __nv_bfloat16* Al;
    int rb; long sO; long sI;
    const __nv_bfloat16* Wh; const __nv_bfloat16* Wl; int ldw;
    const float* bias; const float* Cinit; int ldci;
    float* C; int ldc; int act;
};

__device__ __forceinline__ long mrow(const MP& p, int row) {
    if (p.rb == 0) return (long)row * p.sI;
    int o = row / p.rb;
    int i = row - o * p.rb;
    return (long)o * p.sO + (long)i * p.sI;
}

__device__ __forceinline__ void cpa16(unsigned saddr, const void* g) {
    asm volatile("cp.async.cg.shared.global [%0], [%1], 16;" :: "r"(saddr), "l"(g));
}
__device__ __forceinline__ void ldsm4(unsigned& r0, unsigned& r1,
                                      unsigned& r2, unsigned& r3, unsigned addr) {
    asm volatile("ldmatrix.sync.aligned.m8n8.x4.shared.b16 {%0,%1,%2,%3}, [%4];"
        : "=r"(r0), "=r"(r1), "=r"(r2), "=r"(r3) : "r"(addr));
}
__device__ __forceinline__ void hmma(float* c, const unsigned* a, const unsigned* b) {
    asm volatile("mma.sync.aligned.m16n8k16.row.col.f32.bf16.bf16.f32 "
        "{%0,%1,%2,%3}, {%4,%5,%6,%7}, {%8,%9}, {%0,%1,%2,%3};"
        : "+f"(c[0]), "+f"(c[1]), "+f"(c[2]), "+f"(c[3])
        : "r"(a[0]), "r"(a[1]), "r"(a[2]), "r"(a[3]), "r"(b[0]), "r"(b[1]));
}

#define MPITCH 40            // bf16 per smem row (conflict-free: 80B stride)
#define MTILEB (128*MPITCH*2)

__global__ void __launch_bounds__(256)
mma3_k(MP p0, MP p1, int K)
{
    const MP p = blockIdx.z ? p1 : p0;
    const int bn0 = blockIdx.x * 128;
    const int bm0 = blockIdx.y * 128;

    __shared__ __align__(16) char smem[4 * MTILEB];   // A0,A1,B0,B1
    unsigned sbase = (unsigned)__cvta_generic_to_shared(smem);
    unsigned sA = sbase, sB = sbase + 2 * MTILEB;

    const int tid  = threadIdx.x;
    const int lane = tid & 31, wid = tid >> 5;
    const int wm = (wid & 3) * 32, wn = (wid >> 2) * 64;

    // cp.async loader mapping: thread covers rows r0 and r0+64, 16B segment sg
    const int r0 = tid >> 2;
    const int sg = (tid & 3) * 8;
    const long aoff0 = mrow(p, bm0 + r0) + sg;
    const long aoff1 = mrow(p, bm0 + r0 + 64) + sg;
    const long woff0 = (long)(bn0 + r0) * p.ldw + sg;
    const long woff1 = woff0 + 64L * p.ldw;
    const unsigned dA0 = sA + (r0 * MPITCH + sg) * 2;
    const unsigned dA1 = dA0 + 64 * MPITCH * 2;
    const unsigned dB0 = sB + (r0 * MPITCH + sg) * 2;
    const unsigned dB1 = dB0 + 64 * MPITCH * 2;

    // ldmatrix per-thread address components
    const int g  = lane >> 3, la = lane & 7;
    const int a_r = (g & 1) * 8 + la, a_k = (g >> 1) * 8;
    const int b_r = (g >> 1) * 8 + la, b_k = (g & 1) * 8;

    float acc[2][8][4];
#pragma unroll
    for (int i = 0; i < 2; i++)
#pragma unroll
        for (int j = 0; j < 8; j++)
#pragma unroll
            for (int k = 0; k < 4; k++) acc[i][j][k] = 0.f;

    const int ktiles = K >> 5;
    const int T = 3 * ktiles;

    auto issue = [&](int t, int buf) {
        int pass = (t >= 2 * ktiles) ? 2 : ((t >= ktiles) ? 1 : 0);
        int kt = (t - pass * ktiles) << 5;
        const __nv_bfloat16* Ap = (pass == 2) ? p.Al : p.Ah;
        const __nv_bfloat16* Wp = (pass == 1) ? p.Wl : p.Wh;
        unsigned bo = buf * MTILEB;
        cpa16(dA0 + bo, Ap + aoff0 + kt);
        cpa16(dA1 + bo, Ap + aoff1 + kt);
        cpa16(dB0 + bo, Wp + woff0 + kt);
        cpa16(dB1 + bo, Wp + woff1 + kt);
        asm volatile("cp.async.commit_group;" ::: "memory");
    };

    issue(0, 0);
    int buf = 0;
    for (int t = 0; t < T; t++) {
        asm volatile("cp.async.wait_group 0;" ::: "memory");
        __syncthreads();
        if (t + 1 < T) issue(t + 1, buf ^ 1);
        unsigned bA = sA + buf * MTILEB, bB = sB + buf * MTILEB;
#pragma unroll
        for (int kk = 0; kk < 2; kk++) {
            const int k16 = kk << 4;
            unsigned af[2][4], bf[8][2];
#pragma unroll
            for (int mt = 0; mt < 2; mt++) {
                unsigned ad = bA + (((wm + mt*16 + a_r) * MPITCH) + k16 + a_k) * 2;
                ldsm4(af[mt][0], af[mt][1], af[mt][2], af[mt][3], ad);
            }
#pragma unroll
            for (int np = 0; np < 4; np++) {
                unsigned bd = bB + (((wn + np*16 + b_r) * MPITCH) + k16 + b_k) * 2;
                ldsm4(bf[2*np][0], bf[2*np][1], bf[2*np+1][0], bf[2*np+1][1], bd);
            }
#pragma unroll
            for (int mt = 0; mt < 2; mt++)
#pragma unroll
                for (int nt = 0; nt < 8; nt++)
                    hmma(acc[mt][nt], af[mt], bf[nt]);
        }
        buf ^= 1;
    }

    // epilogue
#pragma unroll
    for (int mt = 0; mt < 2; mt++) {
        int r = bm0 + wm + mt * 16 + (lane >> 2);
#pragma unroll
        for (int nt = 0; nt < 8; nt++) {
            int c = bn0 + wn + nt * 8 + ((lane & 3) << 1);
            float v0 = acc[mt][nt][0], v1 = acc[mt][nt][1];
            float v2 = acc[mt][nt][2], v3 = acc[mt][nt][3];
            if (p.bias) {
                float b0 = p.bias[c], b1 = p.bias[c + 1];
                v0 += b0; v1 += b1; v2 += b0; v3 += b1;
            }
            if (p.Cinit) {
                const float* q0 = p.Cinit + (long)r * p.ldci + c;
                const float* q1 = q0 + 8L * p.ldci;
                v0 += q0[0]; v1 += q0[1]; v2 += q1[0]; v3 += q1[1];
            }
            if (p.act) {
                v0 = (v0 > 0.f) ? v0 : expm1f(v0);
                v1 = (v1 > 0.f) ? v1 : expm1f(v1);
                v2 = (v2 > 0.f) ? v2 : expm1f(v2);
                v3 = (v3 > 0.f) ? v3 : expm1f(v3);
            }
            float2* o0 = (float2*)(p.C + (long)r * p.ldc + c);
            float2* o1 = (float2*)(p.C + (long)(r + 8) * p.ldc + c);
            *o0 = make_float2(v0, v1);
            *o1 = make_float2(v2, v3);
        }
    }
}

// =================== elementwise / conversion kernels =======================
__global__ void zero_k(float* p, int n) {
    int i = blockIdx.x * blockDim.x + threadIdx.x;
    if (i < n) p[i] = 0.f;
}
__global__ void zero16_k(unsigned* p, int n) {
    int i = blockIdx.x * blockDim.x + threadIdx.x;
    if (i < n) p[i] = 0u;
}
// hi/lo bf16 split conversion; src rows lds, dst contiguous cols
__global__ void conv_k(const float* __restrict__ src, int lds, int cols,
                       __nv_bfloat16* __restrict__ h, __nv_bfloat16* __restrict__ l,
                       long n)
{
    long i = (long)blockIdx.x * blockDim.x + threadIdx.x;
    if (i >= n) return;
    long r = i / cols; int c = (int)(i - r * cols);
    float v = src[r * (long)lds + c];
    __nv_bfloat16 hh = __float2bfloat16(v);
    h[i] = hh;
    l[i] = __float2bfloat16(v - __bfloat162float(hh));
}

__device__ __forceinline__ float sigm(float x) { return 1.f / (1.f + expf(-x)); }
__device__ __forceinline__ float softplus_f(float x) {
    return fmaxf(x, 0.f) + log1pf(expf(-fabsf(x)));
}

__global__ void gate_k(const float* __restrict__ gi, const float* __restrict__ gh,
                       const float* __restrict__ bih, const float* __restrict__ bhh,
                       float* __restrict__ h,
                       __nv_bfloat16* __restrict__ h_h, __nv_bfloat16* __restrict__ h_l,
                       float* __restrict__ out_t)
{
    int idx = blockIdx.x * blockDim.x + threadIdx.x;   // 256*1024
    int b = idx >> 10;
    int j = idx & 1023;
    long base = (long)b * 3072;
    float r = sigm(gi[base + j] + bih[j] + gh[base + j] + bhh[j]);
    float z = sigm(gi[base + 1024 + j] + bih[1024 + j] + gh[base + 1024 + j] + bhh[1024 + j]);
    float n = tanhf(gi[base + 2048 + j] + bih[2048 + j]
                    + r * (gh[base + 2048 + j] + bhh[2048 + j]));
    long hi = (long)b * 1024 + j;
    float hn = (1.f - z) * n + z * h[hi];
    h[hi] = hn;
    out_t[(long)b * OUTCOLS + j] = hn;
    __nv_bfloat16 hh = __float2bfloat16(hn);
    h_h[hi] = hh;
    h_l[hi] = __float2bfloat16(hn - __bfloat162float(hh));
}

__global__ void epi_k(const float* __restrict__ part,
                      const float* __restrict__ bp2, const float* __restrict__ bq2,
                      const float* __restrict__ np,  const float* __restrict__ nq,
                      float* __restrict__ out_t, float* __restrict__ s_next)
{
    int idx = blockIdx.x * blockDim.x + threadIdx.x;   // 256*64
    int b = idx >> 6;
    int j = idx & 63;
    const float* pp = part;
    const float* pq = part + 32L * 256 * 128;
    float pmean = 0.f, praw = 0.f, qmean = 0.f, qraw = 0.f;
#pragma unroll
    for (int s = 0; s < 32; s++) {
        const float* rp = pp + (long)s * (256 * 128) + (long)b * 128;
        const float* rq = pq + (long)s * (256 * 128) + (long)b * 128;
        pmean += rp[j];  praw += rp[64 + j];
        qmean += rq[j];  qraw += rq[64 + j];
    }
    pmean += bp2[j];  praw += bp2[64 + j];
    qmean += bq2[j];  qraw += bq2[64 + j];
    float pstd = softplus_f(praw) + 0.1f;
    float qstd = softplus_f(qraw) + 0.1f;
    float pst = pmean + pstd * np[(long)b * 64 + j];
    float qst = qmean + qstd * nq[(long)b * 64 + j];
    float* o = out_t + (long)b * OUTCOLS + 1024;
    o[j]        = pmean;
    o[64  + j]  = pstd;
    o[128 + j]  = pst;
    o[192 + j]  = qmean;
    o[256 + j]  = qstd;
    o[320 + j]  = qst;
    s_next[(long)b * 64 + j] = qst;
}

// =================== host orchestration =====================================
static GP mk(const float* A, int rb, long sO, long sI,
             const float* W, int ldw, const float* bias,
             const float* Cinit, int ldci,
             float* C, int ldc, long ss,
             __nv_bfloat16* Ch = nullptr, __nv_bfloat16* Cl = nullptr)
{
    GP p; p.A=A; p.rb=rb; p.sO=sO; p.sI=sI; p.W=W; p.ldw=ldw; p.bias=bias;
    p.Cinit=Cinit; p.ldci=ldci; p.C=C; p.ldc=ldc; p.splitStride=ss;
    p.Ch=Ch; p.Cl=Cl;
    return p;
}
static MP mkM(const __nv_bfloat16* Ah, const __nv_bfloat16* Al,
              int rb, long sO, long sI,
              const __nv_bfloat16* Wh, const __nv_bfloat16* Wl, int ldw,
              const float* bias, const float* Cinit, int ldci,
              float* C, int ldc, int act)
{
    MP p; p.Ah=Ah; p.Al=Al; p.rb=rb; p.sO=sO; p.sI=sI; p.Wh=Wh; p.Wl=Wl; p.ldw=ldw;
    p.bias=bias; p.Cinit=Cinit; p.ldci=ldci; p.C=C; p.ldc=ldc; p.act=act;
    return p;
}

extern "C" void kernel_launch(void* const* d_in, const int* in_sizes, int n_in,
                              void* d_out, int out_size)
{
    const float* obs  = (const float*)d_in[0];
    const float* act  = (const float*)d_in[1];
    const float* np   = (const float*)d_in[2];
    const float* nq   = (const float*)d_in[3];
    const float* Wsa  = (const float*)d_in[4];
    const float* bsa  = (const float*)d_in[5];
    const float* Wih  = (const float*)d_in[6];
    const float* bih  = (const float*)d_in[7];
    const float* Whh  = (const float*)d_in[8];
    const float* bhh  = (const float*)d_in[9];
    const float* Wp1  = (const float*)d_in[10];
    const float* bp1  = (const float*)d_in[11];
    const float* Wp2  = (const float*)d_in[12];
    const float* bp2  = (const float*)d_in[13];
    const float* Wq1  = (const float*)d_in[14];
    const float* bq1  = (const float*)d_in[15];
    const float* Wq2  = (const float*)d_in[16];
    const float* bq2  = (const float*)d_in[17];
    float* out = (float*)d_out;

    void* fp = nullptr; cudaGetSymbolAddress(&fp, g_f32);
    void* bp = nullptr; cudaGetSymbolAddress(&bp, g_bf16);
    float* F = (float*)fp;
    __nv_bfloat16* Bh = (__nv_bfloat16*)bp;

    float* pre_sa = F + F_PRESA;
    float* pre_q  = F + F_PREQ;
    float* gi_b   = F + F_GI;
    float* gh_b   = F + F_GH;
    float* h_b    = F + F_H;
    float* s_b    = F + F_S;
    float* hp_b   = F + F_HP;
    float* hq_b   = F + F_HQ;
    float* part   = F + F_PART;

    __nv_bfloat16* obs_h = Bh + B_OBSH;
    __nv_bfloat16* obs_l = Bh + B_OBSL;
    __nv_bfloat16* WihH  = Bh + B_WIHH;
    __nv_bfloat16* WihL  = Bh + B_WIHL;
    __nv_bfloat16* WhhH  = Bh + B_WHHH;
    __nv_bfloat16* WhhL  = Bh + B_WHHL;
    __nv_bfloat16* Wp1H  = Bh + B_WP1H;
    __nv_bfloat16* Wp1L  = Bh + B_WP1L;
    __nv_bfloat16* WqcH  = Bh + B_WQCH;
    __nv_bfloat16* WqcL  = Bh + B_WQCL;
    __nv_bfloat16* WqoH  = Bh + B_WQOH;
    __nv_bfloat16* WqoL  = Bh + B_WQOL;
    __nv_bfloat16* e_h   = Bh + B_EH;
    __nv_bfloat16* e_l   = Bh + B_EL;
    __nv_bfloat16* h_h   = Bh + B_HH;
    __nv_bfloat16* h_l   = Bh + B_HL;

    // zero h, s (contiguous) and h hi/lo
    zero_k<<<(278528 + 255) / 256, 256>>>(h_b, 278528);
    zero16_k<<<(262144 + 255) / 256, 256>>>((unsigned*)h_h, 262144);  // h_h + h_l

    // ---- hi/lo conversions (weights + obs), one-time ----
    conv_k<<<(16777216 + 255) / 256, 256>>>(obs, 1024, 1024, obs_h, obs_l, 16777216L);
    conv_k<<<(3145728 + 255) / 256, 256>>>(Wih, 1024, 1024, WihH, WihL, 3145728L);
    conv_k<<<(3145728 + 255) / 256, 256>>>(Whh, 1024, 1024, WhhH, WhhL, 3145728L);
    conv_k<<<(1048576 + 255) / 256, 256>>>(Wp1, 1024, 1024, Wp1H, Wp1L, 1048576L);
    conv_k<<<(1048576 + 255) / 256, 256>>>(Wq1, 2048, 1024, WqcH, WqcL, 1048576L);
    conv_k<<<(1048576 + 255) / 256, 256>>>(Wq1 + 1024, 2048, 1024, WqoH, WqoL, 1048576L);

    // ---- precompute pre_sa (fp32 SIMT, K=32) ----
    {
        GP p = mk(act, 256, 32, 64L * 32, Wsa + 64, 96, bsa,
                  nullptr, 0, pre_sa, 1024, 0);
        gemm2_k<64,64,16,4,4,0,0><<<dim3(16, 252, 1), 256>>>(p, p, 1, 32, 32);
    }
    // ---- precompute pre_q (bf16 MMA, M=16128) ----
    {
        MP p = mkM(obs_h + 1024, obs_l + 1024, 256, 1024, 64L * 1024,
                   WqoH, WqoL, 1024, bq1, nullptr, 0, pre_q, 1024, 0);
        mma3_k<<<dim3(8, 126, 1), 256>>>(p, p, 1024);
    }

    // ---- 63 sequential steps ----
    for (int t = 0; t < TSTEPS; t++) {
        float* out_t = out + (long)t * BATCH * OUTCOLS;

        // e = elu(s @ Wsa[:, :64]^T + pre_sa[t]) -> e hi/lo bf16
        {
            GP p = mk(s_b, 0, 0, 64, Wsa, 96, nullptr,
                      pre_sa + (long)t * 262144, 1024,
                      nullptr, 1024, 0, e_h, e_l);
            gemm2_k<64,64,16,4,4,1,1><<<dim3(16, 4, 1), 256>>>(p, p, 1, 64, 64);
        }
        // gi = e @ Wih^T ; gh = h @ Whh^T   (bf16 MMA 3-term, 96 blocks)
        {
            MP p0 = mkM(e_h, e_l, 0, 0, 1024, WihH, WihL, 1024,
                        nullptr, nullptr, 0, gi_b, 3072, 0);
            MP p1 = mkM(h_h, h_l, 0, 0, 1024, WhhH, WhhL, 1024,
                        nullptr, nullptr, 0, gh_b, 3072, 0);
            mma3_k<<<dim3(24, 2, 2), 256>>>(p0, p1, 1024);
        }
        // GRU gate (adds biases) -> h, h hi/lo, out[:, :1024]
        gate_k<<<1024, 256>>>(gi_b, gh_b, bih, bhh, h_b, h_h, h_l, out_t);

        // hp = elu(h @ Wp1^T + bp1) ; hq = elu(h @ Wq1c^T + pre_q[t])
        {
            MP p0 = mkM(h_h, h_l, 0, 0, 1024, Wp1H, Wp1L, 1024,
                        bp1, nullptr, 0, hp_b, 1024, 1);
            MP p1 = mkM(h_h, h_l, 0, 0, 1024, WqcH, WqcL, 1024,
                        nullptr, pre_q + (long)t * 262144, 1024, hq_b, 1024, 1);
            mma3_k<<<dim3(8, 2, 2), 256>>>(p0, p1, 1024);
        }
        // pm/qm partials (fp32 split-K=32)
        {
            GP p0 = mk(hp_b, 0, 0, 1024, Wp2, 1024, nullptr, nullptr, 0,
                       part, 128, 256L * 128);
            GP p1 = mk(hq_b, 0, 0, 1024, Wq2, 1024, nullptr, nullptr, 0,
                       part + 32L * 256 * 128, 128, 256L * 128);
            gemm2_k<128,128,16,8,8,0,0><<<dim3(1, 2, 64), 256>>>(p0, p1, 32, 32, 32);
        }
        // reduce + softplus + reparam
        epi_k<<<64, 256>>>(part, bp2, bq2,
                           np + (long)t * BATCH * 64,
                           nq + (long)t * BATCH * 64,
                           out_t, s_b);
    }
}

// round 14
// speedup vs baseline: 1.6559x; 1.0011x over previous
#include <cuda_runtime.h>
#include <cuda_bf16.h>
#include <math.h>

// ---------------------------------------------------------------------------
// RSSM observe_rollout: B=256, T=64 (63 steps), D=1024, S=64, A=32, E=1024, H=1024
// Output: [63, 256, 1408] fp32
// R12: big GEMMs on bf16 tensor cores (mma.sync m16n8k16) with hi/lo 3-term
//      compensated split; cp.async double buffering + ldmatrix.
// ---------------------------------------------------------------------------

#define TSTEPS   63
#define BATCH    256
#define OUTCOLS  1408

// ---------------- f32 scratch ----------------
#define F_PRESA  0L            // 63*256*1024
#define F_PREQ   16515072L     // 63*256*1024
#define F_GI     33030144L     // 256*3072
#define F_GH     33816576L     // 256*3072
#define F_H      34603008L     // 256*1024
#define F_S      34865152L     // 256*64
#define F_HP     34881536L     // 256*1024
#define F_HQ     35143680L     // 256*1024
#define F_PART   35405824L     // 2*32*256*128
#define F_TOTAL  37502976L
__device__ float g_f32[F_TOTAL];

// ---------------- bf16 scratch ----------------
#define B_OBSH   0L            // 256*64*1024
#define B_OBSL   16777216L
#define B_WIHH   33554432L     // 3072*1024
#define B_WIHL   36700160L
#define B_WHHH   39845888L
#define B_WHHL   42991616L
#define B_WP1H   46137344L     // 1024*1024
#define B_WP1L   47185920L
#define B_WQCH   48234496L     // Wq1[:, :1024]
#define B_WQCL   49283072L
#define B_WQOH   50331648L     // Wq1[:, 1024:2048]
#define B_WQOL   51380224L
#define B_EH     52428800L     // 256*1024
#define B_EL     52690944L
#define B_HH     52953088L     // 256*1024
#define B_HL     53215232L
#define B_TOTAL  53477376L
__device__ __nv_bfloat16 g_bf16[B_TOTAL];

// =================== fp32 SIMT GEMM (small ops) =============================
typedef unsigned long long u64t;
__device__ __forceinline__ u64t pack2(float x, float y) {
    u64t r; asm("mov.b64 %0, {%1, %2};" : "=l"(r) : "f"(x), "f"(y)); return r;
}
__device__ __forceinline__ void unpack2(u64t v, float& x, float& y) {
    asm("mov.b64 {%0, %1}, %2;" : "=f"(x), "=f"(y) : "l"(v));
}
__device__ __forceinline__ void fma2(u64t& c, u64t a, u64t b) {
    asm("fma.rn.f32x2 %0, %1, %2, %0;" : "+l"(c) : "l"(a), "l"(b));
}

struct GP {
    const float* A;  int rb;  long sO;  long sI;
    const float* W;  int ldw;
    const float* bias;
    const float* Cinit; int ldci;
    float* C; int ldc; long splitStride;
    __nv_bfloat16* Ch; __nv_bfloat16* Cl;
};

__device__ __forceinline__ const float* rowp(const GP& p, int row) {
    if (p.rb == 0) return p.A + (long)row * p.sI;
    int o = row / p.rb;
    int i = row - o * p.rb;
    return p.A + (long)o * p.sO + (long)i * p.sI;
}

template<int BM, int BN, int BK, int TM, int TN, int ACT, int OH>
__global__ void __launch_bounds__((BM/TM)*(BN/TN))
gemm2_k(GP p0, GP p1, int nsplit, int kc0, int kcr)
{
    constexpr int NT  = (BM/TM)*(BN/TN);
    constexpr int KF4 = BK/4;
    const GP p = (blockIdx.z / nsplit) ? p1 : p0;
    const int split = blockIdx.z % nsplit;
    const int kBeg  = (split == 0) ? 0 : kc0 + (split - 1) * kcr;
    const int kcur  = (split == 0) ? kc0 : kcr;
    const int bn0 = blockIdx.x * BN;
    const int bm0 = blockIdx.y * BM;

    __shared__ float As[BK][BM + 4];
    __shared__ float Bs[BK][BN + 4];

    u64t acc2[TM][TN/2];
#pragma unroll
    for (int i = 0; i < TM; i++)
#pragma unroll
        for (int j = 0; j < TN/2; j++) acc2[i][j] = 0ULL;

    const int tid = threadIdx.x;
    const int tx  = tid % (BN/TN);
    const int ty  = tid / (BN/TN);

    for (int kt = kBeg; kt < kBeg + kcur; kt += BK) {
#pragma unroll
        for (int it = 0; it < (BM*BK/4)/NT; it++) {
            int i  = tid + it*NT;
            int r  = i / KF4;
            int c4 = i % KF4;
            const float* ap = rowp(p, bm0 + r) + kt + c4*4;
            float4 v = *reinterpret_cast<const float4*>(ap);
            As[c4*4+0][r] = v.x; As[c4*4+1][r] = v.y;
            As[c4*4+2][r] = v.z; As[c4*4+3][r] = v.w;
        }
#pragma unroll
        for (int it = 0; it < (BN*BK/4)/NT; it++) {
            int i  = tid + it*NT;
            int n  = i / KF4;
            int c4 = i % KF4;
            float4 v = *reinterpret_cast<const float4*>(
                p.W + (long)(bn0 + n) * p.ldw + kt + c4*4);
            Bs[c4*4+0][n] = v.x; Bs[c4*4+1][n] = v.y;
            Bs[c4*4+2][n] = v.z; Bs[c4*4+3][n] = v.w;
        }
        __syncthreads();

#pragma unroll
        for (int k = 0; k < BK; k++) {
            float a[TM];
            u64t  b2[TN/2];
#pragma unroll
            for (int i = 0; i < TM; i += 4) {
                float4 v = *reinterpret_cast<const float4*>(&As[k][ty*TM + i]);
                a[i]=v.x; a[i+1]=v.y; a[i+2]=v.z; a[i+3]=v.w;
            }
#pragma unroll
            for (int j = 0; j < TN; j += 4) {
                float4 v = *reinterpret_cast<const float4*>(&Bs[k][tx*TN + j]);
                b2[j/2]     = pack2(v.x, v.y);
                b2[j/2 + 1] = pack2(v.z, v.w);
            }
#pragma unroll
            for (int i = 0; i < TM; i++) {
                u64t a2 = pack2(a[i], a[i]);
#pragma unroll
                for (int jp = 0; jp < TN/2; jp++)
                    fma2(acc2[i][jp], a2, b2[jp]);
            }
        }
        __syncthreads();
    }

    float* Cp = p.C ? p.C + (long)split * p.splitStride : nullptr;
#pragma unroll
    for (int i = 0; i < TM; i++) {
        int row = bm0 + ty*TM + i;
#pragma unroll
        for (int jp = 0; jp < TN/2; jp++) {
            float c0, c1;
            unpack2(acc2[i][jp], c0, c1);
            int col = bn0 + tx*TN + 2*jp;
            if (p.bias)  { c0 += p.bias[col]; c1 += p.bias[col+1]; }
            if (p.Cinit) {
                const float* ci = p.Cinit + (long)row * p.ldci + col;
                c0 += ci[0]; c1 += ci[1];
            }
            if (ACT) {
                c0 = (c0 > 0.f) ? c0 : expm1f(c0);
                c1 = (c1 > 0.f) ? c1 : expm1f(c1);
            }
            if (OH) {
                __nv_bfloat16 h0 = __float2bfloat16(c0);
                __nv_bfloat16 h1 = __float2bfloat16(c1);
                long o = (long)row * p.ldc + col;
                p.Ch[o]   = h0;
                p.Ch[o+1] = h1;
                p.Cl[o]   = __float2bfloat16(c0 - __bfloat162float(h0));
                p.Cl[o+1] = __float2bfloat16(c1 - __bfloat162float(h1));
            } else {
                float* cp = Cp + (long)row * p.ldc + col;
                cp[0] = c0; cp[1] = c1;
            }
        }
    }
}

// =================== bf16 3-term MMA GEMM ===================================
struct MP {
    const __nv_bfloat16* Ah; const __nv_bfloat16* Al;
    int rb; long sO; long sI;
    const __nv_bfloat16* Wh; const __nv_bfloat16* Wl; int ldw;
    const float* bias; const float* Cinit; int ldci;
    float* C; int ldc; int act;
};

__device__ __forceinline__ long mrow(const MP& p, int row) {
    if (p.rb == 0) return (long)row * p.sI;
    int o = row / p.rb;
    int i = row - o * p.rb;
    return (long)o * p.sO + (long)i * p.sI;
}

__device__ __forceinline__ void cpa16(unsigned saddr, const void* g) {
    asm volatile("cp.async.cg.shared.global [%0], [%1], 16;" :: "r"(saddr), "l"(g));
}
__device__ __forceinline__ void ldsm4(unsigned& r0, unsigned& r1,
                                      unsigned& r2, unsigned& r3, unsigned addr) {
    asm volatile("ldmatrix.sync.aligned.m8n8.x4.shared.b16 {%0,%1,%2,%3}, [%4];"
        : "=r"(r0), "=r"(r1), "=r"(r2), "=r"(r3) : "r"(addr));
}
__device__ __forceinline__ void hmma(float* c, const unsigned* a, const unsigned* b) {
    asm volatile("mma.sync.aligned.m16n8k16.row.col.f32.bf16.bf16.f32 "
        "{%0,%1,%2,%3}, {%4,%5,%6,%7}, {%8,%9}, {%0,%1,%2,%3};"
        : "+f"(c[0]), "+f"(c[1]), "+f"(c[2]), "+f"(c[3])
        : "r"(a[0]), "r"(a[1]), "r"(a[2]), "r"(a[3]), "r"(b[0]), "r"(b[1]));
}

#define MPITCH 40            // bf16 per smem row (conflict-free: 80B stride)
#define MTILEB (128*MPITCH*2)

__global__ void __launch_bounds__(256)
mma3_k(MP p0, MP p1, int K)
{
    const MP p = blockIdx.z ? p1 : p0;
    const int bn0 = blockIdx.x * 128;
    const int bm0 = blockIdx.y * 128;

    __shared__ __align__(16) char smem[4 * MTILEB];   // A0,A1,B0,B1
    unsigned sbase = (unsigned)__cvta_generic_to_shared(smem);
    unsigned sA = sbase, sB = sbase + 2 * MTILEB;

    const int tid  = threadIdx.x;
    const int lane = tid & 31, wid = tid >> 5;
    const int wm = (wid & 3) * 32, wn = (wid >> 2) * 64;

    // cp.async loader mapping: thread covers rows r0 and r0+64, 16B segment sg
    const int r0 = tid >> 2;
    const int sg = (tid & 3) * 8;
    const long aoff0 = mrow(p, bm0 + r0) + sg;
    const long aoff1 = mrow(p, bm0 + r0 + 64) + sg;
    const long woff0 = (long)(bn0 + r0) * p.ldw + sg;
    const long woff1 = woff0 + 64L * p.ldw;
    const unsigned dA0 = sA + (r0 * MPITCH + sg) * 2;
    const unsigned dA1 = dA0 + 64 * MPITCH * 2;
    const unsigned dB0 = sB + (r0 * MPITCH + sg) * 2;
    const unsigned dB1 = dB0 + 64 * MPITCH * 2;

    // ldmatrix per-thread address components
    const int g  = lane >> 3, la = lane & 7;
    const int a_r = (g & 1) * 8 + la, a_k = (g >> 1) * 8;
    const int b_r = (g >> 1) * 8 + la, b_k = (g & 1) * 8;

    float acc[2][8][4];
#pragma unroll
    for (int i = 0; i < 2; i++)
#pragma unroll
        for (int j = 0; j < 8; j++)
#pragma unroll
            for (int k = 0; k < 4; k++) acc[i][j][k] = 0.f;

    const int ktiles = K >> 5;
    const int T = 3 * ktiles;

    auto issue = [&](int t, int buf) {
        int pass = (t >= 2 * ktiles) ? 2 : ((t >= ktiles) ? 1 : 0);
        int kt = (t - pass * ktiles) << 5;
        const __nv_bfloat16* Ap = (pass == 2) ? p.Al : p.Ah;
        const __nv_bfloat16* Wp = (pass == 1) ? p.Wl : p.Wh;
        unsigned bo = buf * MTILEB;
        cpa16(dA0 + bo, Ap + aoff0 + kt);
        cpa16(dA1 + bo, Ap + aoff1 + kt);
        cpa16(dB0 + bo, Wp + woff0 + kt);
        cpa16(dB1 + bo, Wp + woff1 + kt);
        asm volatile("cp.async.commit_group;" ::: "memory");
    };

    issue(0, 0);
    int buf = 0;
    for (int t = 0; t < T; t++) {
        asm volatile("cp.async.wait_group 0;" ::: "memory");
        __syncthreads();
        if (t + 1 < T) issue(t + 1, buf ^ 1);
        unsigned bA = sA + buf * MTILEB, bB = sB + buf * MTILEB;
#pragma unroll
        for (int kk = 0; kk < 2; kk++) {
            const int k16 = kk << 4;
            unsigned af[2][4], bf[8][2];
#pragma unroll
            for (int mt = 0; mt < 2; mt++) {
                unsigned ad = bA + (((wm + mt*16 + a_r) * MPITCH) + k16 + a_k) * 2;
                ldsm4(af[mt][0], af[mt][1], af[mt][2], af[mt][3], ad);
            }
#pragma unroll
            for (int np = 0; np < 4; np++) {
                unsigned bd = bB + (((wn + np*16 + b_r) * MPITCH) + k16 + b_k) * 2;
                ldsm4(bf[2*np][0], bf[2*np][1], bf[2*np+1][0], bf[2*np+1][1], bd);
            }
#pragma unroll
            for (int mt = 0; mt < 2; mt++)
#pragma unroll
                for (int nt = 0; nt < 8; nt++)
                    hmma(acc[mt][nt], af[mt], bf[nt]);
        }
        buf ^= 1;
    }

    // epilogue
#pragma unroll
    for (int mt = 0; mt < 2; mt++) {
        int r = bm0 + wm + mt * 16 + (lane >> 2);
#pragma unroll
        for (int nt = 0; nt < 8; nt++) {
            int c = bn0 + wn + nt * 8 + ((lane & 3) << 1);
            float v0 = acc[mt][nt][0], v1 = acc[mt][nt][1];
            float v2 = acc[mt][nt][2], v3 = acc[mt][nt][3];
            if (p.bias) {
                float b0 = p.bias[c], b1 = p.bias[c + 1];
                v0 += b0; v1 += b1; v2 += b0; v3 += b1;
            }
            if (p.Cinit) {
                const float* q0 = p.Cinit + (long)r * p.ldci + c;
                const float* q1 = q0 + 8L * p.ldci;
                v0 += q0[0]; v1 += q0[1]; v2 += q1[0]; v3 += q1[1];
            }
            if (p.act) {
                v0 = (v0 > 0.f) ? v0 : expm1f(v0);
                v1 = (v1 > 0.f) ? v1 : expm1f(v1);
                v2 = (v2 > 0.f) ? v2 : expm1f(v2);
                v3 = (v3 > 0.f) ? v3 : expm1f(v3);
            }
            float2* o0 = (float2*)(p.C + (long)r * p.ldc + c);
            float2* o1 = (float2*)(p.C + (long)(r + 8) * p.ldc + c);
            *o0 = make_float2(v0, v1);
            *o1 = make_float2(v2, v3);
        }
    }
}

// =================== elementwise / conversion kernels =======================
__global__ void zero_k(float* p, int n) {
    int i = blockIdx.x * blockDim.x + threadIdx.x;
    if (i < n) p[i] = 0.f;
}
__global__ void zero16_k(unsigned* p, int n) {
    int i = blockIdx.x * blockDim.x + threadIdx.x;
    if (i < n) p[i] = 0u;
}
// hi/lo bf16 split conversion; src rows lds, dst contiguous cols
__global__ void conv_k(const float* __restrict__ src, int lds, int cols,
                       __nv_bfloat16* __restrict__ h, __nv_bfloat16* __restrict__ l,
                       long n)
{
    long i = (long)blockIdx.x * blockDim.x + threadIdx.x;
    if (i >= n) return;
    long r = i / cols; int c = (int)(i - r * cols);
    float v = src[r * (long)lds + c];
    __nv_bfloat16 hh = __float2bfloat16(v);
    h[i] = hh;
    l[i] = __float2bfloat16(v - __bfloat162float(hh));
}

__device__ __forceinline__ float sigm(float x) { return 1.f / (1.f + expf(-x)); }
__device__ __forceinline__ float softplus_f(float x) {
    return fmaxf(x, 0.f) + log1pf(expf(-fabsf(x)));
}

__global__ void gate_k(const float* __restrict__ gi, const float* __restrict__ gh,
                       const float* __restrict__ bih, const float* __restrict__ bhh,
                       float* __restrict__ h,
                       __nv_bfloat16* __restrict__ h_h, __nv_bfloat16* __restrict__ h_l,
                       float* __restrict__ out_t)
{
    int idx = blockIdx.x * blockDim.x + threadIdx.x;   // 256*1024
    int b = idx >> 10;
    int j = idx & 1023;
    long base = (long)b * 3072;
    float r = sigm(gi[base + j] + bih[j] + gh[base + j] + bhh[j]);
    float z = sigm(gi[base + 1024 + j] + bih[1024 + j] + gh[base + 1024 + j] + bhh[1024 + j]);
    float n = tanhf(gi[base + 2048 + j] + bih[2048 + j]
                    + r * (gh[base + 2048 + j] + bhh[2048 + j]));
    long hi = (long)b * 1024 + j;
    float hn = (1.f - z) * n + z * h[hi];
    h[hi] = hn;
    out_t[(long)b * OUTCOLS + j] = hn;
    __nv_bfloat16 hh = __float2bfloat16(hn);
    h_h[hi] = hh;
    h_l[hi] = __float2bfloat16(hn - __bfloat162float(hh));
}

__global__ void epi_k(const float* __restrict__ part,
                      const float* __restrict__ bp2, const float* __restrict__ bq2,
                      const float* __restrict__ np,  const float* __restrict__ nq,
                      float* __restrict__ out_t, float* __restrict__ s_next)
{
    int idx = blockIdx.x * blockDim.x + threadIdx.x;   // 256*64
    int b = idx >> 6;
    int j = idx & 63;
    const float* pp = part;
    const float* pq = part + 32L * 256 * 128;
    float pmean = 0.f, praw = 0.f, qmean = 0.f, qraw = 0.f;
#pragma unroll
    for (int s = 0; s < 32; s++) {
        const float* rp = pp + (long)s * (256 * 128) + (long)b * 128;
        const float* rq = pq + (long)s * (256 * 128) + (long)b * 128;
        pmean += rp[j];  praw += rp[64 + j];
        qmean += rq[j];  qraw += rq[64 + j];
    }
    pmean += bp2[j];  praw += bp2[64 + j];
    qmean += bq2[j];  qraw += bq2[64 + j];
    float pstd = softplus_f(praw) + 0.1f;
    float qstd = softplus_f(qraw) + 0.1f;
    float pst = pmean + pstd * np[(long)b * 64 + j];
    float qst = qmean + qstd * nq[(long)b * 64 + j];
    float* o = out_t + (long)b * OUTCOLS + 1024;
    o[j]        = pmean;
    o[64  + j]  = pstd;
    o[128 + j]  = pst;
    o[192 + j]  = qmean;
    o[256 + j]  = qstd;
    o[320 + j]  = qst;
    s_next[(long)b * 64 + j] = qst;
}

// =================== host orchestration =====================================
static GP mk(const float* A, int rb, long sO, long sI,
             const float* W, int ldw, const float* bias,
             const float* Cinit, int ldci,
             float* C, int ldc, long ss,
             __nv_bfloat16* Ch = nullptr, __nv_bfloat16* Cl = nullptr)
{
    GP p; p.A=A; p.rb=rb; p.sO=sO; p.sI=sI; p.W=W; p.ldw=ldw; p.bias=bias;
    p.Cinit=Cinit; p.ldci=ldci; p.C=C; p.ldc=ldc; p.splitStride=ss;
    p.Ch=Ch; p.Cl=Cl;
    return p;
}
static MP mkM(const __nv_bfloat16* Ah, const __nv_bfloat16* Al,
              int rb, long sO, long sI,
              const __nv_bfloat16* Wh, const __nv_bfloat16* Wl, int ldw,
              const float* bias, const float* Cinit, int ldci,
              float* C, int ldc, int act)
{
    MP p; p.Ah=Ah; p.Al=Al; p.rb=rb; p.sO=sO; p.sI=sI; p.Wh=Wh; p.Wl=Wl; p.ldw=ldw;
    p.bias=bias; p.Cinit=Cinit; p.ldci=ldci; p.C=C; p.ldc=ldc; p.act=act;
    return p;
}

extern "C" void kernel_launch(void* const* d_in, const int* in_sizes, int n_in,
                              void* d_out, int out_size)
{
    const float* obs  = (const float*)d_in[0];
    const float* act  = (const float*)d_in[1];
    const float* np   = (const float*)d_in[2];
    const float* nq   = (const float*)d_in[3];
    const float* Wsa  = (const float*)d_in[4];
    const float* bsa  = (const float*)d_in[5];
    const float* Wih  = (const float*)d_in[6];
    const float* bih  = (const float*)d_in[7];
    const float* Whh  = (const float*)d_in[8];
    const float* bhh  = (const float*)d_in[9];
    const float* Wp1  = (const float*)d_in[10];
    const float* bp1  = (const float*)d_in[11];
    const float* Wp2  = (const float*)d_in[12];
    const float* bp2  = (const float*)d_in[13];
    const float* Wq1  = (const float*)d_in[14];
    const float* bq1  = (const float*)d_in[15];
    const float* Wq2  = (const float*)d_in[16];
    const float* bq2  = (const float*)d_in[17];
    float* out = (float*)d_out;

    void* fp = nullptr; cudaGetSymbolAddress(&fp, g_f32);
    void* bp = nullptr; cudaGetSymbolAddress(&bp, g_bf16);
    float* F = (float*)fp;
    __nv_bfloat16* Bh = (__nv_bfloat16*)bp;

    float* pre_sa = F + F_PRESA;
    float* pre_q  = F + F_PREQ;
    float* gi_b   = F + F_GI;
    float* gh_b   = F + F_GH;
    float* h_b    = F + F_H;
    float* s_b    = F + F_S;
    float* hp_b   = F + F_HP;
    float* hq_b   = F + F_HQ;
    float* part   = F + F_PART;

    __nv_bfloat16* obs_h = Bh + B_OBSH;
    __nv_bfloat16* obs_l = Bh + B_OBSL;
    __nv_bfloat16* WihH  = Bh + B_WIHH;
    __nv_bfloat16* WihL  = Bh + B_WIHL;
    __nv_bfloat16* WhhH  = Bh + B_WHHH;
    __nv_bfloat16* WhhL  = Bh + B_WHHL;
    __nv_bfloat16* Wp1H  = Bh + B_WP1H;
    __nv_bfloat16* Wp1L  = Bh + B_WP1L;
    __nv_bfloat16* WqcH  = Bh + B_WQCH;
    __nv_bfloat16* WqcL  = Bh + B_WQCL;
    __nv_bfloat16* WqoH  = Bh + B_WQOH;
    __nv_bfloat16* WqoL  = Bh + B_WQOL;
    __nv_bfloat16* e_h   = Bh + B_EH;
    __nv_bfloat16* e_l   = Bh + B_EL;
    __nv_bfloat16* h_h   = Bh + B_HH;
    __nv_bfloat16* h_l   = Bh + B_HL;

    // zero h, s (contiguous) and h hi/lo
    zero_k<<<(278528 + 255) / 256, 256>>>(h_b, 278528);
    zero16_k<<<(262144 + 255) / 256, 256>>>((unsigned*)h_h, 262144);  // h_h + h_l

    // ---- hi/lo conversions (weights + obs), one-time ----
    conv_k<<<(16777216 + 255) / 256, 256>>>(obs, 1024, 1024, obs_h, obs_l, 16777216L);
    conv_k<<<(3145728 + 255) / 256, 256>>>(Wih, 1024, 1024, WihH, WihL, 3145728L);
    conv_k<<<(3145728 + 255) / 256, 256>>>(Whh, 1024, 1024, WhhH, WhhL, 3145728L);
    conv_k<<<(1048576 + 255) / 256, 256>>>(Wp1, 1024, 1024, Wp1H, Wp1L, 1048576L);
    conv_k<<<(1048576 + 255) / 256, 256>>>(Wq1, 2048, 1024, WqcH, WqcL, 1048576L);
    conv_k<<<(1048576 + 255) / 256, 256>>>(Wq1 + 1024, 2048, 1024, WqoH, WqoL, 1048576L);

    // ---- precompute pre_sa (fp32 SIMT, K=32) ----
    {
        GP p = mk(act, 256, 32, 64L * 32, Wsa + 64, 96, bsa,
                  nullptr, 0, pre_sa, 1024, 0);
        gemm2_k<64,64,16,4,4,0,0><<<dim3(16, 252, 1), 256>>>(p, p, 1, 32, 32);
    }
    // ---- precompute pre_q (bf16 MMA, M=16128) ----
    {
        MP p = mkM(obs_h + 1024, obs_l + 1024, 256, 1024, 64L * 1024,
                   WqoH, WqoL, 1024, bq1, nullptr, 0, pre_q, 1024, 0);
        mma3_k<<<dim3(8, 126, 1), 256>>>(p, p, 1024);
    }

    // ---- 63 sequential steps ----
    for (int t = 0; t < TSTEPS; t++) {
        float* out_t = out + (long)t * BATCH * OUTCOLS;

        // e = elu(s @ Wsa[:, :64]^T + pre_sa[t]) -> e hi/lo bf16
        {
            GP p = mk(s_b, 0, 0, 64, Wsa, 96, nullptr,
                      pre_sa + (long)t * 262144, 1024,
                      nullptr, 1024, 0, e_h, e_l);
            gemm2_k<64,64,16,4,4,1,1><<<dim3(16, 4, 1), 256>>>(p, p, 1, 64, 64);
        }
        // gi = e @ Wih^T ; gh = h @ Whh^T   (bf16 MMA 3-term, 96 blocks)
        {
            MP p0 = mkM(e_h, e_l, 0, 0, 1024, WihH, WihL, 1024,
                        nullptr, nullptr, 0, gi_b, 3072, 0);
            MP p1 = mkM(h_h, h_l, 0, 0, 1024, WhhH, WhhL, 1024,
                        nullptr, nullptr, 0, gh_b, 3072, 0);
            mma3_k<<<dim3(24, 2, 2), 256>>>(p0, p1, 1024);
        }
        // GRU gate (adds biases) -> h, h hi/lo, out[:, :1024]
        gate_k<<<1024, 256>>>(gi_b, gh_b, bih, bhh, h_b, h_h, h_l, out_t);

        // hp = elu(h @ Wp1^T + bp1) ; hq = elu(h @ Wq1c^T + pre_q[t])
        {
            MP p0 = mkM(h_h, h_l, 0, 0, 1024, Wp1H, Wp1L, 1024,
                        bp1, nullptr, 0, hp_b, 1024, 1);
            MP p1 = mkM(h_h, h_l, 0, 0, 1024, WqcH, WqcL, 1024,
                        nullptr, pre_q + (long)t * 262144, 1024, hq_b, 1024, 1);
            mma3_k<<<dim3(8, 2, 2), 256>>>(p0, p1, 1024);
        }
        // pm/qm partials (fp32 split-K=32)
        {
            GP p0 = mk(hp_b, 0, 0, 1024, Wp2, 1024, nullptr, nullptr, 0,
                       part, 128, 256L * 128);
            GP p1 = mk(hq_b, 0, 0, 1024, Wq2, 1024, nullptr, nullptr, 0,
                       part + 32L * 256 * 128, 128, 256L * 128);
            gemm2_k<128,128,16,8,8,0,0><<<dim3(1, 2, 64), 256>>>(p0, p1, 32, 32, 32);
        }
        // reduce + softplus + reparam
        epi_k<<<64, 256>>>(part, bp2, bq2,
                           np + (long)t * BATCH * 64,
                           nq + (long)t * BATCH * 64,
                           out_t, s_b);
    }
}